// round 12
// baseline (speedup 1.0000x reference)
#include <cuda_runtime.h>
#include <cuda_fp16.h>
#include <math.h>
#include <stdint.h>

// GMM log-likelihood via mma.sync fp16 (sm_100 baseline PTX).
// out[b] = logsumexp_k( off_k - 0.5*||L_k x_b - m_k||^2 ), m_k = L_k mu_k.
// L lower-triangular: only j-chunk <= i-chunk tiles computed/loaded.
// 8 warps = 2 wm (32 rows) x 4 npair; warp npair owns i-chunks {n, 7-n}.
// FUSED-PAIR mainloop: both chunks' MMAs interleaved over the shared
// k-range -> 8 independent accumulator chains (vs 4); small chunk's fused
// epilogue emitted early to release its acc registers before the tail.
// Prefetch uses an exact triangle enumeration (2 threads/row, c=(t&1)+2j,
// j<=row/16) -> zero wasted predicated cp.async slots.
// A fragments register-resident across all 16 components. 2 CTAs/SM.

#define NK 16
#define D 128
#define BR 64
#define THREADS 256
#define PASSES 16

#define XS_BYTES 272
#define SM_X 0                               // 64*272 = 17408
#define SM_L 17408
#define LBUF_BYTES (128 * XS_BYTES)          // 34816 (1 comp)
#define SM_M (SM_L + 2 * LBUF_BYTES)         // 87040 : float m[16][128]
#define SM_OFFS (SM_M + NK * D * 4)          // 95232 : float off[16]
#define SM_SRED (SM_OFFS + 64)               // 95296 : float [4][16][64]
#define SM_TOTAL (SM_SRED + 4 * NK * BR * 4) // 111680

__device__ __half g_Lh[NK * D * D];
__device__ float g_m[NK][D];
__device__ float g_off[NK];

// ---------------- fused prep: cvt fp16 + m_k + off_k ----------------
__global__ void gmm_prep_kernel(const float* __restrict__ means,
                                const float* __restrict__ prec,
                                const float* __restrict__ logw) {
    const int k = blockIdx.x;
    const int tid = threadIdx.x;
    const int wid = tid >> 5, lane = tid & 31;
    const float* Lk = prec + (size_t)k * D * D;

    __shared__ float mu_s[D];
    __shared__ float red[D];

    if (tid < D) mu_s[tid] = means[k * D + tid];
    if (tid < D) red[tid] = logf(Lk[tid * D + tid]);

    {
        const float4* s4 = (const float4*)Lk;
        uint2* d4 = (uint2*)(g_Lh + (size_t)k * D * D);
        #pragma unroll
        for (int i = 0; i < 16; ++i) {
            float4 v = s4[tid + i * 256];
            __half2 h0 = __floats2half2_rn(v.x, v.y);
            __half2 h1 = __floats2half2_rn(v.z, v.w);
            d4[tid + i * 256] = make_uint2(*(uint32_t*)&h0, *(uint32_t*)&h1);
        }
    }
    __syncthreads();

    for (int r = wid; r < D; r += 8) {
        float4 v = ((const float4*)(Lk + r * D))[lane];
        float4 m4 = *(const float4*)&mu_s[lane * 4];
        float d = v.x * m4.x + v.y * m4.y + v.z * m4.z + v.w * m4.w;
        #pragma unroll
        for (int o = 16; o > 0; o >>= 1) d += __shfl_xor_sync(~0u, d, o);
        if (lane == 0) g_m[k][r] = d;
    }

    for (int off = D / 2; off > 0; off >>= 1) {
        if (tid < off) red[tid] += red[tid + off];
        __syncthreads();
    }
    if (tid == 0)
        g_off[k] = logw[k] + red[0] - 64.0f * 1.8378770664093453f;
}

// ---------------- asm helpers ----------------
__device__ __forceinline__ uint32_t smem_u32(const void* p) {
    uint32_t a;
    asm("{ .reg .u64 t; cvta.to.shared.u64 t, %1; cvt.u32.u64 %0, t; }"
        : "=r"(a) : "l"(p));
    return a;
}
__device__ __forceinline__ void ldsm_x4(uint32_t& r0, uint32_t& r1,
                                        uint32_t& r2, uint32_t& r3,
                                        uint32_t addr) {
    asm volatile("ldmatrix.sync.aligned.m8n8.x4.shared.b16 {%0,%1,%2,%3}, [%4];"
                 : "=r"(r0), "=r"(r1), "=r"(r2), "=r"(r3) : "r"(addr));
}
__device__ __forceinline__ void mma_f16(float* c, uint32_t a0, uint32_t a1,
                                        uint32_t a2, uint32_t a3,
                                        uint32_t b0, uint32_t b1) {
    asm volatile(
        "mma.sync.aligned.m16n8k16.row.col.f32.f16.f16.f32 "
        "{%0,%1,%2,%3}, {%4,%5,%6,%7}, {%8,%9}, {%0,%1,%2,%3};"
        : "+f"(c[0]), "+f"(c[1]), "+f"(c[2]), "+f"(c[3])
        : "r"(a0), "r"(a1), "r"(a2), "r"(a3), "r"(b0), "r"(b1));
}
__device__ __forceinline__ void cp16(uint32_t dst, const void* src) {
    asm volatile("cp.async.cg.shared.global [%0], [%1], 16;"
                 :: "r"(dst), "l"(src) : "memory");
}

// Prefetch one component's L (fp16, lower triangle only), exact enumeration:
// 2 threads per row; thread covers chunks c=(t&1)+2j, j=0..g (g=row/16),
// i.e. exactly c in [0, 2g+1] -> no predicated-off cp.async slots.
__device__ __forceinline__ void prefetch_L(uint32_t dstb, const char* src,
                                           int tid) {
    const int r = tid >> 1;
    const int g = r >> 4;
    const uint32_t drow = dstb + r * XS_BYTES + (tid & 1) * 16;
    const char* srow = src + r * 256 + (tid & 1) * 16;
    for (int j = 0; j <= g; ++j)
        cp16(drow + j * 32, srow + j * 32);
    asm volatile("cp.async.commit_group;" ::: "memory");
}

// Fused epilogue for one chunk: subtract m, square, accumulate into rl/rh.
__device__ __forceinline__ void epi_chunk(const float acc[2][2][4], int IC,
                                          const char* m_base, int lane,
                                          float rl[2], float rh[2]) {
    #pragma unroll
    for (int mf = 0; mf < 2; ++mf)
        #pragma unroll
        for (int nf = 0; nf < 2; ++nf) {
            float2 mv = *(const float2*)(m_base + (IC * 16 + nf * 8) * 4 +
                                         (lane & 3) * 8);
            float v0 = acc[mf][nf][0] - mv.x;
            float v1 = acc[mf][nf][1] - mv.y;
            float v2 = acc[mf][nf][2] - mv.x;
            float v3 = acc[mf][nf][3] - mv.y;
            rl[mf] = fmaf(v0, v0, fmaf(v1, v1, rl[mf]));
            rh[mf] = fmaf(v2, v2, fmaf(v3, v3, rh[mf]));
        }
}

// Fused pair {ICA, ICB} (ICA >= ICB): shared s-range runs both chunks'
// MMAs (8 acc chains); chunk-B epilogue early (frees accB); tail runs
// chunk A alone; chunk-A epilogue.
template <int ICA, int ICB>
__device__ __forceinline__ void do_pair(const uint32_t afr[2][8][4],
                                        uint32_t lb, const char* m_base,
                                        int lane, float rl[2], float rh[2]) {
    float accA[2][2][4], accB[2][2][4];
    #pragma unroll
    for (int mf = 0; mf < 2; ++mf)
        #pragma unroll
        for (int nf = 0; nf < 2; ++nf)
            #pragma unroll
            for (int q = 0; q < 4; ++q) {
                accA[mf][nf][q] = 0.f;
                accB[mf][nf][q] = 0.f;
            }

    #pragma unroll
    for (int s = 0; s <= ICB; ++s) {
        uint32_t a0, a1, a2, a3, c0, c1, c2, c3;
        ldsm_x4(a0, a1, a2, a3, lb + ICA * (16 * XS_BYTES) + s * 32);
        ldsm_x4(c0, c1, c2, c3, lb + ICB * (16 * XS_BYTES) + s * 32);
        #pragma unroll
        for (int mf = 0; mf < 2; ++mf) {
            mma_f16(accA[mf][0], afr[mf][s][0], afr[mf][s][1], afr[mf][s][2],
                    afr[mf][s][3], a0, a1);
            mma_f16(accA[mf][1], afr[mf][s][0], afr[mf][s][1], afr[mf][s][2],
                    afr[mf][s][3], a2, a3);
            mma_f16(accB[mf][0], afr[mf][s][0], afr[mf][s][1], afr[mf][s][2],
                    afr[mf][s][3], c0, c1);
            mma_f16(accB[mf][1], afr[mf][s][0], afr[mf][s][1], afr[mf][s][2],
                    afr[mf][s][3], c2, c3);
        }
    }

    epi_chunk(accB, ICB, m_base, lane, rl, rh);   // accB dies here

    #pragma unroll
    for (int s = ICB + 1; s <= ICA; ++s) {
        uint32_t a0, a1, a2, a3;
        ldsm_x4(a0, a1, a2, a3, lb + ICA * (16 * XS_BYTES) + s * 32);
        #pragma unroll
        for (int mf = 0; mf < 2; ++mf) {
            mma_f16(accA[mf][0], afr[mf][s][0], afr[mf][s][1], afr[mf][s][2],
                    afr[mf][s][3], a0, a1);
            mma_f16(accA[mf][1], afr[mf][s][0], afr[mf][s][1], afr[mf][s][2],
                    afr[mf][s][3], a2, a3);
        }
    }

    epi_chunk(accA, ICA, m_base, lane, rl, rh);
}

extern __shared__ char smem[];

__global__ __launch_bounds__(THREADS, 2)
void gmm_f16_kernel(const float* __restrict__ x, float* __restrict__ out) {
    const int tid = threadIdx.x;
    const int wid = tid >> 5;
    const int lane = tid & 31;
    const int wm = wid >> 2;          // 0..1 : 32-row M tile
    const int npair = wid & 3;        // i-chunk pair {npair, 7-npair}
    const uint32_t sbase = smem_u32(smem);

    // --- prefetch L comp 0 ---
    prefetch_L(sbase + SM_L, (const char*)g_Lh, tid);

    // --- stage X (fp32 -> fp16): 64 rows ---
    {
        const float4* xg = (const float4*)(x + (size_t)blockIdx.x * BR * D);
        #pragma unroll
        for (int i = 0; i < 8; ++i) {
            int f = tid + i * THREADS;
            float4 v = xg[f];
            __half2 h0 = __floats2half2_rn(v.x, v.y);
            __half2 h1 = __floats2half2_rn(v.z, v.w);
            int r = f >> 5, c4 = f & 31;
            *(uint2*)(smem + SM_X + r * XS_BYTES + c4 * 8) =
                make_uint2(*(uint32_t*)&h0, *(uint32_t*)&h1);
        }
    }
    // --- stage m, off ---
    {
        const float* gm = (const float*)g_m;
        #pragma unroll
        for (int i = 0; i < 8; ++i)
            ((float*)(smem + SM_M))[tid + i * THREADS] = gm[tid + i * THREADS];
        if (tid < NK) ((float*)(smem + SM_OFFS))[tid] = g_off[tid];
    }
    asm volatile("cp.async.wait_group 0;" ::: "memory");
    __syncthreads();

    const uint32_t a_lane = (uint32_t)((lane & 15) * XS_BYTES + (lane >> 4) * 16);
    const uint32_t b_lane = (uint32_t)(((lane >> 4) * 8 + (lane & 7)) * XS_BYTES +
                                       ((lane >> 3) & 1) * 16);
    const uint32_t aw = sbase + SM_X + wm * 32 * XS_BYTES + a_lane;

    // --- A fragments: 32 rows x K=128, loaded ONCE for all 16 components ---
    uint32_t afr[2][8][4];
    #pragma unroll
    for (int mf = 0; mf < 2; ++mf)
        #pragma unroll
        for (int s = 0; s < 8; ++s)
            ldsm_x4(afr[mf][s][0], afr[mf][s][1], afr[mf][s][2], afr[mf][s][3],
                    aw + mf * (16 * XS_BYTES) + s * 32);

    for (int p = 0; p < PASSES; ++p) {
        if (p + 1 < PASSES)
            prefetch_L(sbase + SM_L + ((p + 1) & 1) * LBUF_BYTES,
                       (const char*)g_Lh + (size_t)(p + 1) * 32768, tid);

        const uint32_t lb = sbase + SM_L + (p & 1) * LBUF_BYTES + b_lane;
        const char* m_base = smem + SM_M + p * D * 4;

        float rl[2] = {0.f, 0.f}, rh[2] = {0.f, 0.f};
        switch (npair) {
            case 0:  do_pair<7, 0>(afr, lb, m_base, lane, rl, rh); break;
            case 1:  do_pair<6, 1>(afr, lb, m_base, lane, rl, rh); break;
            case 2:  do_pair<5, 2>(afr, lb, m_base, lane, rl, rh); break;
            default: do_pair<4, 3>(afr, lb, m_base, lane, rl, rh); break;
        }

        // --- quad-reduce and write-once SRED[npair][p][row] ---
        float* sredw = (float*)(smem + SM_SRED) + (npair * NK + p) * BR;
        #pragma unroll
        for (int mf = 0; mf < 2; ++mf) {
            float lo = rl[mf], hi = rh[mf];
            lo += __shfl_xor_sync(~0u, lo, 1);
            lo += __shfl_xor_sync(~0u, lo, 2);
            hi += __shfl_xor_sync(~0u, hi, 1);
            hi += __shfl_xor_sync(~0u, hi, 2);
            if ((lane & 3) == 0) {
                int row = wm * 32 + mf * 16 + (lane >> 2);
                sredw[row] = lo;
                sredw[row + 8] = hi;
            }
        }

        if (p + 1 < PASSES) {
            asm volatile("cp.async.wait_group 0;" ::: "memory");
            __syncthreads();   // L[p+1] visible; buf (p+1)&1 reads done
        }
    }

    __syncthreads();   // all SRED writes visible

    if (tid < BR) {
        const float* sred = (const float*)(smem + SM_SRED);
        const float* offs = (const float*)(smem + SM_OFFS);
        float v[NK], mx = -INFINITY;
        #pragma unroll
        for (int k = 0; k < NK; ++k) {
            float s = sred[k * BR + tid] + sred[(NK + k) * BR + tid] +
                      sred[(2 * NK + k) * BR + tid] +
                      sred[(3 * NK + k) * BR + tid];
            v[k] = offs[k] - 0.5f * s;
            mx = fmaxf(mx, v[k]);
        }
        float e = 0.f;
        #pragma unroll
        for (int k = 0; k < NK; ++k) e += expf(v[k] - mx);
        out[blockIdx.x * BR + tid] = mx + logf(e);
    }
}

extern "C" void kernel_launch(void* const* d_in, const int* in_sizes, int n_in,
                              void* d_out, int out_size) {
    const float* x     = (const float*)d_in[0];
    const float* means = (const float*)d_in[1];
    const float* prec  = (const float*)d_in[2];
    const float* logw  = (const float*)d_in[3];
    float* out = (float*)d_out;

    const int B = in_sizes[0] / D;

    gmm_prep_kernel<<<NK, 256>>>(means, prec, logw);

    cudaFuncSetAttribute(gmm_f16_kernel,
                         cudaFuncAttributeMaxDynamicSharedMemorySize, SM_TOTAL);
    gmm_f16_kernel<<<B / BR, THREADS, SM_TOTAL>>>(x, out);
}

// round 13
// speedup vs baseline: 1.1868x; 1.1868x over previous
#include <cuda_runtime.h>
#include <cuda_fp16.h>
#include <math.h>
#include <stdint.h>

// GMM log-likelihood via mma.sync fp16 (sm_100 baseline PTX).
// out[b] = logsumexp_k( off_k - 0.5*||L_k x_b - m_k||^2 ), m_k = L_k mu_k.
// L lower-triangular: only j-chunk <= i-chunk tiles computed/loaded.
// 8 warps = 2 wm (32 rows) x 4 npair; warp npair owns i-chunks {n, 7-n}.
// FUSED-PAIR mainloop: both chunks' MMAs interleaved over the shared
// k-range -> 8 independent accumulator chains; small chunk's fused epilogue
// emitted early to release its acc registers before the tail.
// Prefetch: R11-style COALESCED predicated triangle load (contiguous 256B
// per 16 threads; the R12 "exact" enumeration broke coalescing -> +44% L2).
// A fragments register-resident across all 16 components. 2 CTAs/SM.

#define NK 16
#define D 128
#define BR 64
#define THREADS 256
#define PASSES 16

#define XS_BYTES 272
#define SM_X 0                               // 64*272 = 17408
#define SM_L 17408
#define LBUF_BYTES (128 * XS_BYTES)          // 34816 (1 comp)
#define SM_M (SM_L + 2 * LBUF_BYTES)         // 87040 : float m[16][128]
#define SM_OFFS (SM_M + NK * D * 4)          // 95232 : float off[16]
#define SM_SRED (SM_OFFS + 64)               // 95296 : float [4][16][64]
#define SM_TOTAL (SM_SRED + 4 * NK * BR * 4) // 111680

__device__ __half g_Lh[NK * D * D];
__device__ float g_m[NK][D];
__device__ float g_off[NK];

// ---------------- fused prep: cvt fp16 + m_k + off_k ----------------
__global__ void gmm_prep_kernel(const float* __restrict__ means,
                                const float* __restrict__ prec,
                                const float* __restrict__ logw) {
    const int k = blockIdx.x;
    const int tid = threadIdx.x;
    const int wid = tid >> 5, lane = tid & 31;
    const float* Lk = prec + (size_t)k * D * D;

    __shared__ float mu_s[D];
    __shared__ float red[D];

    if (tid < D) mu_s[tid] = means[k * D + tid];
    if (tid < D) red[tid] = logf(Lk[tid * D + tid]);

    {
        const float4* s4 = (const float4*)Lk;
        uint2* d4 = (uint2*)(g_Lh + (size_t)k * D * D);
        #pragma unroll
        for (int i = 0; i < 16; ++i) {
            float4 v = s4[tid + i * 256];
            __half2 h0 = __floats2half2_rn(v.x, v.y);
            __half2 h1 = __floats2half2_rn(v.z, v.w);
            d4[tid + i * 256] = make_uint2(*(uint32_t*)&h0, *(uint32_t*)&h1);
        }
    }
    __syncthreads();

    for (int r = wid; r < D; r += 8) {
        float4 v = ((const float4*)(Lk + r * D))[lane];
        float4 m4 = *(const float4*)&mu_s[lane * 4];
        float d = v.x * m4.x + v.y * m4.y + v.z * m4.z + v.w * m4.w;
        #pragma unroll
        for (int o = 16; o > 0; o >>= 1) d += __shfl_xor_sync(~0u, d, o);
        if (lane == 0) g_m[k][r] = d;
    }

    for (int off = D / 2; off > 0; off >>= 1) {
        if (tid < off) red[tid] += red[tid + off];
        __syncthreads();
    }
    if (tid == 0)
        g_off[k] = logw[k] + red[0] - 64.0f * 1.8378770664093453f;
}

// ---------------- asm helpers ----------------
__device__ __forceinline__ uint32_t smem_u32(const void* p) {
    uint32_t a;
    asm("{ .reg .u64 t; cvta.to.shared.u64 t, %1; cvt.u32.u64 %0, t; }"
        : "=r"(a) : "l"(p));
    return a;
}
__device__ __forceinline__ void ldsm_x4(uint32_t& r0, uint32_t& r1,
                                        uint32_t& r2, uint32_t& r3,
                                        uint32_t addr) {
    asm volatile("ldmatrix.sync.aligned.m8n8.x4.shared.b16 {%0,%1,%2,%3}, [%4];"
                 : "=r"(r0), "=r"(r1), "=r"(r2), "=r"(r3) : "r"(addr));
}
__device__ __forceinline__ void mma_f16(float* c, uint32_t a0, uint32_t a1,
                                        uint32_t a2, uint32_t a3,
                                        uint32_t b0, uint32_t b1) {
    asm volatile(
        "mma.sync.aligned.m16n8k16.row.col.f32.f16.f16.f32 "
        "{%0,%1,%2,%3}, {%4,%5,%6,%7}, {%8,%9}, {%0,%1,%2,%3};"
        : "+f"(c[0]), "+f"(c[1]), "+f"(c[2]), "+f"(c[3])
        : "r"(a0), "r"(a1), "r"(a2), "r"(a3), "r"(b0), "r"(b1));
}
__device__ __forceinline__ void cp16(uint32_t dst, const void* src) {
    asm volatile("cp.async.cg.shared.global [%0], [%1], 16;"
                 :: "r"(dst), "l"(src) : "memory");
}

// Prefetch one component's L (fp16, lower triangle only): coalesced
// predicated form (16 consecutive threads cover one row's 16 chunks ->
// contiguous 256B runs; predicate keeps only c <= 2*(r/16)+1).
__device__ __forceinline__ void prefetch_L(uint32_t dstb, const char* src,
                                           int tid) {
    #pragma unroll
    for (int i = 0; i < 8; ++i) {
        int idx = tid + i * THREADS;
        int r = idx >> 4, c = idx & 15;          // c: 16B chunk (8 halves)
        if (c <= 2 * (r >> 4) + 1)               // lower-triangle chunks only
            cp16(dstb + r * XS_BYTES + c * 16, src + r * 256 + c * 16);
    }
    asm volatile("cp.async.commit_group;" ::: "memory");
}

// Fused epilogue for one chunk: subtract m, square, accumulate into rl/rh.
__device__ __forceinline__ void epi_chunk(const float acc[2][2][4], int IC,
                                          const char* m_base, int lane,
                                          float rl[2], float rh[2]) {
    #pragma unroll
    for (int mf = 0; mf < 2; ++mf)
        #pragma unroll
        for (int nf = 0; nf < 2; ++nf) {
            float2 mv = *(const float2*)(m_base + (IC * 16 + nf * 8) * 4 +
                                         (lane & 3) * 8);
            float v0 = acc[mf][nf][0] - mv.x;
            float v1 = acc[mf][nf][1] - mv.y;
            float v2 = acc[mf][nf][2] - mv.x;
            float v3 = acc[mf][nf][3] - mv.y;
            rl[mf] = fmaf(v0, v0, fmaf(v1, v1, rl[mf]));
            rh[mf] = fmaf(v2, v2, fmaf(v3, v3, rh[mf]));
        }
}

// Fused pair {ICA, ICB} (ICA >= ICB): shared s-range runs both chunks'
// MMAs (8 acc chains); chunk-B epilogue early (frees accB); tail runs
// chunk A alone; chunk-A epilogue.
template <int ICA, int ICB>
__device__ __forceinline__ void do_pair(const uint32_t afr[2][8][4],
                                        uint32_t lb, const char* m_base,
                                        int lane, float rl[2], float rh[2]) {
    float accA[2][2][4], accB[2][2][4];
    #pragma unroll
    for (int mf = 0; mf < 2; ++mf)
        #pragma unroll
        for (int nf = 0; nf < 2; ++nf)
            #pragma unroll
            for (int q = 0; q < 4; ++q) {
                accA[mf][nf][q] = 0.f;
                accB[mf][nf][q] = 0.f;
            }

    #pragma unroll
    for (int s = 0; s <= ICB; ++s) {
        uint32_t a0, a1, a2, a3, c0, c1, c2, c3;
        ldsm_x4(a0, a1, a2, a3, lb + ICA * (16 * XS_BYTES) + s * 32);
        ldsm_x4(c0, c1, c2, c3, lb + ICB * (16 * XS_BYTES) + s * 32);
        #pragma unroll
        for (int mf = 0; mf < 2; ++mf) {
            mma_f16(accA[mf][0], afr[mf][s][0], afr[mf][s][1], afr[mf][s][2],
                    afr[mf][s][3], a0, a1);
            mma_f16(accA[mf][1], afr[mf][s][0], afr[mf][s][1], afr[mf][s][2],
                    afr[mf][s][3], a2, a3);
            mma_f16(accB[mf][0], afr[mf][s][0], afr[mf][s][1], afr[mf][s][2],
                    afr[mf][s][3], c0, c1);
            mma_f16(accB[mf][1], afr[mf][s][0], afr[mf][s][1], afr[mf][s][2],
                    afr[mf][s][3], c2, c3);
        }
    }

    epi_chunk(accB, ICB, m_base, lane, rl, rh);   // accB dies here

    #pragma unroll
    for (int s = ICB + 1; s <= ICA; ++s) {
        uint32_t a0, a1, a2, a3;
        ldsm_x4(a0, a1, a2, a3, lb + ICA * (16 * XS_BYTES) + s * 32);
        #pragma unroll
        for (int mf = 0; mf < 2; ++mf) {
            mma_f16(accA[mf][0], afr[mf][s][0], afr[mf][s][1], afr[mf][s][2],
                    afr[mf][s][3], a0, a1);
            mma_f16(accA[mf][1], afr[mf][s][0], afr[mf][s][1], afr[mf][s][2],
                    afr[mf][s][3], a2, a3);
        }
    }

    epi_chunk(accA, ICA, m_base, lane, rl, rh);
}

extern __shared__ char smem[];

__global__ __launch_bounds__(THREADS, 2)
void gmm_f16_kernel(const float* __restrict__ x, float* __restrict__ out) {
    const int tid = threadIdx.x;
    const int wid = tid >> 5;
    const int lane = tid & 31;
    const int wm = wid >> 2;          // 0..1 : 32-row M tile
    const int npair = wid & 3;        // i-chunk pair {npair, 7-npair}
    const uint32_t sbase = smem_u32(smem);

    // --- prefetch L comp 0 ---
    prefetch_L(sbase + SM_L, (const char*)g_Lh, tid);

    // --- stage X (fp32 -> fp16): 64 rows ---
    {
        const float4* xg = (const float4*)(x + (size_t)blockIdx.x * BR * D);
        #pragma unroll
        for (int i = 0; i < 8; ++i) {
            int f = tid + i * THREADS;
            float4 v = xg[f];
            __half2 h0 = __floats2half2_rn(v.x, v.y);
            __half2 h1 = __floats2half2_rn(v.z, v.w);
            int r = f >> 5, c4 = f & 31;
            *(uint2*)(smem + SM_X + r * XS_BYTES + c4 * 8) =
                make_uint2(*(uint32_t*)&h0, *(uint32_t*)&h1);
        }
    }
    // --- stage m, off ---
    {
        const float* gm = (const float*)g_m;
        #pragma unroll
        for (int i = 0; i < 8; ++i)
            ((float*)(smem + SM_M))[tid + i * THREADS] = gm[tid + i * THREADS];
        if (tid < NK) ((float*)(smem + SM_OFFS))[tid] = g_off[tid];
    }
    asm volatile("cp.async.wait_group 0;" ::: "memory");
    __syncthreads();

    const uint32_t a_lane = (uint32_t)((lane & 15) * XS_BYTES + (lane >> 4) * 16);
    const uint32_t b_lane = (uint32_t)(((lane >> 4) * 8 + (lane & 7)) * XS_BYTES +
                                       ((lane >> 3) & 1) * 16);
    const uint32_t aw = sbase + SM_X + wm * 32 * XS_BYTES + a_lane;

    // --- A fragments: 32 rows x K=128, loaded ONCE for all 16 components ---
    uint32_t afr[2][8][4];
    #pragma unroll
    for (int mf = 0; mf < 2; ++mf)
        #pragma unroll
        for (int s = 0; s < 8; ++s)
            ldsm_x4(afr[mf][s][0], afr[mf][s][1], afr[mf][s][2], afr[mf][s][3],
                    aw + mf * (16 * XS_BYTES) + s * 32);

    for (int p = 0; p < PASSES; ++p) {
        if (p + 1 < PASSES)
            prefetch_L(sbase + SM_L + ((p + 1) & 1) * LBUF_BYTES,
                       (const char*)g_Lh + (size_t)(p + 1) * 32768, tid);

        const uint32_t lb = sbase + SM_L + (p & 1) * LBUF_BYTES + b_lane;
        const char* m_base = smem + SM_M + p * D * 4;

        float rl[2] = {0.f, 0.f}, rh[2] = {0.f, 0.f};
        switch (npair) {
            case 0:  do_pair<7, 0>(afr, lb, m_base, lane, rl, rh); break;
            case 1:  do_pair<6, 1>(afr, lb, m_base, lane, rl, rh); break;
            case 2:  do_pair<5, 2>(afr, lb, m_base, lane, rl, rh); break;
            default: do_pair<4, 3>(afr, lb, m_base, lane, rl, rh); break;
        }

        // --- quad-reduce and write-once SRED[npair][p][row] ---
        float* sredw = (float*)(smem + SM_SRED) + (npair * NK + p) * BR;
        #pragma unroll
        for (int mf = 0; mf < 2; ++mf) {
            float lo = rl[mf], hi = rh[mf];
            lo += __shfl_xor_sync(~0u, lo, 1);
            lo += __shfl_xor_sync(~0u, lo, 2);
            hi += __shfl_xor_sync(~0u, hi, 1);
            hi += __shfl_xor_sync(~0u, hi, 2);
            if ((lane & 3) == 0) {
                int row = wm * 32 + mf * 16 + (lane >> 2);
                sredw[row] = lo;
                sredw[row + 8] = hi;
            }
        }

        if (p + 1 < PASSES) {
            asm volatile("cp.async.wait_group 0;" ::: "memory");
            __syncthreads();   // L[p+1] visible; buf (p+1)&1 reads done
        }
    }

    __syncthreads();   // all SRED writes visible

    if (tid < BR) {
        const float* sred = (const float*)(smem + SM_SRED);
        const float* offs = (const float*)(smem + SM_OFFS);
        float v[NK], mx = -INFINITY;
        #pragma unroll
        for (int k = 0; k < NK; ++k) {
            float s = sred[k * BR + tid] + sred[(NK + k) * BR + tid] +
                      sred[(2 * NK + k) * BR + tid] +
                      sred[(3 * NK + k) * BR + tid];
            v[k] = offs[k] - 0.5f * s;
            mx = fmaxf(mx, v[k]);
        }
        float e = 0.f;
        #pragma unroll
        for (int k = 0; k < NK; ++k) e += expf(v[k] - mx);
        out[blockIdx.x * BR + tid] = mx + logf(e);
    }
}

extern "C" void kernel_launch(void* const* d_in, const int* in_sizes, int n_in,
                              void* d_out, int out_size) {
    const float* x     = (const float*)d_in[0];
    const float* means = (const float*)d_in[1];
    const float* prec  = (const float*)d_in[2];
    const float* logw  = (const float*)d_in[3];
    float* out = (float*)d_out;

    const int B = in_sizes[0] / D;

    gmm_prep_kernel<<<NK, 256>>>(means, prec, logw);

    cudaFuncSetAttribute(gmm_f16_kernel,
                         cudaFuncAttributeMaxDynamicSharedMemorySize, SM_TOTAL);
    gmm_f16_kernel<<<B / BR, THREADS, SM_TOTAL>>>(x, out);
}

// round 14
// speedup vs baseline: 1.2083x; 1.0181x over previous
#include <cuda_runtime.h>
#include <cuda_fp16.h>
#include <math.h>
#include <stdint.h>

// GMM log-likelihood via mma.sync fp16 (sm_100 baseline PTX).
// out[b] = logsumexp_k( off_k - 0.5*||L_k x_b - m_k||^2 ), m_k = L_k mu_k.
// L lower-triangular. Canonical chunk enumeration (g=i-chunk group, 16 rows,
// 2g+2 16B-chunks per row) packs the triangle DENSELY in global (18KB/comp):
// main prefetch = 4-5 unpredicated cp.async with linear src + precomputed
// dst offsets (2 packed u16x2 regs + closed form). npair dispatch hoisted
// out of the pass loop. MMA accumulators INIT to -m (epilogue = pure x*x).
// Fused-pair mainloop {n,7-n}: 8 acc chains; A frags register-resident.
// BR=64, 256 threads, 2 CTAs/SM.

#define NK 16
#define D 128
#define BR 64
#define THREADS 256
#define PASSES 16

#define XS_BYTES 272
#define SM_X 0                               // 64*272 = 17408
#define SM_L 17408
#define LBUF_BYTES (128 * XS_BYTES)          // 34816 (1 comp)
#define SM_M (SM_L + 2 * LBUF_BYTES)         // 87040 : float m[16][128]
#define SM_OFFS (SM_M + NK * D * 4)          // 95232 : float off[16]
#define SM_SRED (SM_OFFS + 64)               // 95296 : float [4][16][64]
#define SM_TOTAL (SM_SRED + 4 * NK * BR * 4) // 111680

#define NCHUNK 1152                          // triangle chunks (16B each)
#define PACK_BYTES (NCHUNK * 16)             // 18432 per component

__device__ __half g_Lp[NK * NCHUNK * 8];     // packed triangle, fp16
__device__ float g_m[NK][D];
__device__ float g_off[NK];

// canonical chunk idx -> (row, chunk-col)
__device__ __forceinline__ void chunk_rc(int idx, int& r, int& c) {
    int rem = idx;
    r = 0; c = 0;
    #pragma unroll
    for (int g = 0; g < 8; ++g) {
        int cnt = 16 * (2 * g + 2);
        if (rem >= 0 && rem < cnt) {
            r = 16 * g + rem / (2 * g + 2);
            c = rem % (2 * g + 2);
        }
        rem -= cnt;
    }
}

// ---------------- fused prep: pack fp16 triangle + m_k + off_k ----------------
__global__ void gmm_prep_kernel(const float* __restrict__ means,
                                const float* __restrict__ prec,
                                const float* __restrict__ logw) {
    const int k = blockIdx.x;
    const int tid = threadIdx.x;
    const int wid = tid >> 5, lane = tid & 31;
    const float* Lk = prec + (size_t)k * D * D;

    __shared__ float mu_s[D];
    __shared__ float red[D];

    if (tid < D) mu_s[tid] = means[k * D + tid];
    if (tid < D) red[tid] = logf(Lk[tid * D + tid]);

    // pack lower-triangle chunks densely (fp32 -> fp16)
    for (int idx = tid; idx < NCHUNK; idx += THREADS) {
        int r, c;
        chunk_rc(idx, r, c);
        const float4* s = (const float4*)(Lk + r * D + c * 8);
        float4 v0 = s[0], v1 = s[1];
        __half2 h0 = __floats2half2_rn(v0.x, v0.y);
        __half2 h1 = __floats2half2_rn(v0.z, v0.w);
        __half2 h2 = __floats2half2_rn(v1.x, v1.y);
        __half2 h3 = __floats2half2_rn(v1.z, v1.w);
        uint4 o = make_uint4(*(uint32_t*)&h0, *(uint32_t*)&h1,
                             *(uint32_t*)&h2, *(uint32_t*)&h3);
        *(uint4*)(g_Lp + (size_t)k * NCHUNK * 8 + idx * 8) = o;
    }
    __syncthreads();

    for (int r = wid; r < D; r += 8) {
        float4 v = ((const float4*)(Lk + r * D))[lane];
        float4 m4 = *(const float4*)&mu_s[lane * 4];
        float d = v.x * m4.x + v.y * m4.y + v.z * m4.z + v.w * m4.w;
        #pragma unroll
        for (int o = 16; o > 0; o >>= 1) d += __shfl_xor_sync(~0u, d, o);
        if (lane == 0) g_m[k][r] = d;
    }

    for (int off = D / 2; off > 0; off >>= 1) {
        if (tid < off) red[tid] += red[tid + off];
        __syncthreads();
    }
    if (tid == 0)
        g_off[k] = logw[k] + red[0] - 64.0f * 1.8378770664093453f;
}

// ---------------- asm helpers ----------------
__device__ __forceinline__ uint32_t smem_u32(const void* p) {
    uint32_t a;
    asm("{ .reg .u64 t; cvta.to.shared.u64 t, %1; cvt.u32.u64 %0, t; }"
        : "=r"(a) : "l"(p));
    return a;
}
__device__ __forceinline__ void ldsm_x4(uint32_t& r0, uint32_t& r1,
                                        uint32_t& r2, uint32_t& r3,
                                        uint32_t addr) {
    asm volatile("ldmatrix.sync.aligned.m8n8.x4.shared.b16 {%0,%1,%2,%3}, [%4];"
                 : "=r"(r0), "=r"(r1), "=r"(r2), "=r"(r3) : "r"(addr));
}
__device__ __forceinline__ void mma_f16(float* c, uint32_t a0, uint32_t a1,
                                        uint32_t a2, uint32_t a3,
                                        uint32_t b0, uint32_t b1) {
    asm volatile(
        "mma.sync.aligned.m16n8k16.row.col.f32.f16.f16.f32 "
        "{%0,%1,%2,%3}, {%4,%5,%6,%7}, {%8,%9}, {%0,%1,%2,%3};"
        : "+f"(c[0]), "+f"(c[1]), "+f"(c[2]), "+f"(c[3])
        : "r"(a0), "r"(a1), "r"(a2), "r"(a3), "r"(b0), "r"(b1));
}
__device__ __forceinline__ void cp16(uint32_t dst, const void* src) {
    asm volatile("cp.async.cg.shared.global [%0], [%1], 16;"
                 :: "r"(dst), "l"(src) : "memory");
}

// Prefetch one component's packed triangle: linear src, precomputed dst.
__device__ __forceinline__ void prefetch_L(uint32_t dstb, const char* srcp,
                                           uint32_t pk0, uint32_t pk1,
                                           uint32_t off4, int tid) {
    cp16(dstb + (pk0 & 0xFFFFu), srcp);
    cp16(dstb + (pk0 >> 16),     srcp + 4096);
    cp16(dstb + (pk1 & 0xFFFFu), srcp + 8192);
    cp16(dstb + (pk1 >> 16),     srcp + 12288);
    if (tid < 128) cp16(dstb + off4, srcp + 16384);
    asm volatile("cp.async.commit_group;" ::: "memory");
}

// Square-only epilogue (m already folded into accumulator init).
__device__ __forceinline__ void epi_sq(const float acc[2][2][4],
                                       float rl[2], float rh[2]) {
    #pragma unroll
    for (int mf = 0; mf < 2; ++mf)
        #pragma unroll
        for (int nf = 0; nf < 2; ++nf) {
            rl[mf] = fmaf(acc[mf][nf][0], acc[mf][nf][0],
                     fmaf(acc[mf][nf][1], acc[mf][nf][1], rl[mf]));
            rh[mf] = fmaf(acc[mf][nf][2], acc[mf][nf][2],
                     fmaf(acc[mf][nf][3], acc[mf][nf][3], rh[mf]));
        }
}

// Fused pair {ICA, ICB} (ICA >= ICB): acc INIT to -m; shared s-range runs
// both chunks' MMAs (8 chains); chunk-B epilogue early; tail = chunk A.
template <int ICA, int ICB>
__device__ __forceinline__ void do_pair(const uint32_t afr[2][8][4],
                                        uint32_t lb, const char* m_base,
                                        int lane, float rl[2], float rh[2]) {
    float2 mA0 = *(const float2*)(m_base + ICA * 64 + (lane & 3) * 8);
    float2 mA1 = *(const float2*)(m_base + ICA * 64 + 32 + (lane & 3) * 8);
    float2 mB0 = *(const float2*)(m_base + ICB * 64 + (lane & 3) * 8);
    float2 mB1 = *(const float2*)(m_base + ICB * 64 + 32 + (lane & 3) * 8);

    float accA[2][2][4], accB[2][2][4];
    #pragma unroll
    for (int mf = 0; mf < 2; ++mf) {
        accA[mf][0][0] = -mA0.x; accA[mf][0][1] = -mA0.y;
        accA[mf][0][2] = -mA0.x; accA[mf][0][3] = -mA0.y;
        accA[mf][1][0] = -mA1.x; accA[mf][1][1] = -mA1.y;
        accA[mf][1][2] = -mA1.x; accA[mf][1][3] = -mA1.y;
        accB[mf][0][0] = -mB0.x; accB[mf][0][1] = -mB0.y;
        accB[mf][0][2] = -mB0.x; accB[mf][0][3] = -mB0.y;
        accB[mf][1][0] = -mB1.x; accB[mf][1][1] = -mB1.y;
        accB[mf][1][2] = -mB1.x; accB[mf][1][3] = -mB1.y;
    }

    #pragma unroll
    for (int s = 0; s <= ICB; ++s) {
        uint32_t a0, a1, a2, a3, c0, c1, c2, c3;
        ldsm_x4(a0, a1, a2, a3, lb + ICA * (16 * XS_BYTES) + s * 32);
        ldsm_x4(c0, c1, c2, c3, lb + ICB * (16 * XS_BYTES) + s * 32);
        #pragma unroll
        for (int mf = 0; mf < 2; ++mf) {
            mma_f16(accA[mf][0], afr[mf][s][0], afr[mf][s][1], afr[mf][s][2],
                    afr[mf][s][3], a0, a1);
            mma_f16(accA[mf][1], afr[mf][s][0], afr[mf][s][1], afr[mf][s][2],
                    afr[mf][s][3], a2, a3);
            mma_f16(accB[mf][0], afr[mf][s][0], afr[mf][s][1], afr[mf][s][2],
                    afr[mf][s][3], c0, c1);
            mma_f16(accB[mf][1], afr[mf][s][0], afr[mf][s][1], afr[mf][s][2],
                    afr[mf][s][3], c2, c3);
        }
    }

    epi_sq(accB, rl, rh);   // accB dies here

    #pragma unroll
    for (int s = ICB + 1; s <= ICA; ++s) {
        uint32_t a0, a1, a2, a3;
        ldsm_x4(a0, a1, a2, a3, lb + ICA * (16 * XS_BYTES) + s * 32);
        #pragma unroll
        for (int mf = 0; mf < 2; ++mf) {
            mma_f16(accA[mf][0], afr[mf][s][0], afr[mf][s][1], afr[mf][s][2],
                    afr[mf][s][3], a0, a1);
            mma_f16(accA[mf][1], afr[mf][s][0], afr[mf][s][1], afr[mf][s][2],
                    afr[mf][s][3], a2, a3);
        }
    }

    epi_sq(accA, rl, rh);
}

// Whole pass loop for one warp role (npair == ICB). Barriers are structurally
// identical across instantiations (one per iteration, all threads).
template <int ICA, int ICB>
__device__ __forceinline__ void run_passes(const uint32_t afr[2][8][4],
                                           char* smemc, uint32_t sbase,
                                           uint32_t b_lane, uint32_t pk0,
                                           uint32_t pk1, uint32_t off4,
                                           int tid, int lane, int wm) {
    #pragma unroll 1
    for (int p = 0; p < PASSES; ++p) {
        if (p + 1 < PASSES)
            prefetch_L(sbase + SM_L + ((p + 1) & 1) * LBUF_BYTES,
                       (const char*)g_Lp + (size_t)(p + 1) * PACK_BYTES +
                           tid * 16,
                       pk0, pk1, off4, tid);

        const uint32_t lb = sbase + SM_L + (p & 1) * LBUF_BYTES + b_lane;
        const char* m_base = smemc + SM_M + p * 512;

        float rl[2] = {0.f, 0.f}, rh[2] = {0.f, 0.f};
        do_pair<ICA, ICB>(afr, lb, m_base, lane, rl, rh);

        float* sredw = (float*)(smemc + SM_SRED) + (ICB * NK + p) * BR;
        #pragma unroll
        for (int mf = 0; mf < 2; ++mf) {
            float lo = rl[mf], hi = rh[mf];
            lo += __shfl_xor_sync(~0u, lo, 1);
            lo += __shfl_xor_sync(~0u, lo, 2);
            hi += __shfl_xor_sync(~0u, hi, 1);
            hi += __shfl_xor_sync(~0u, hi, 2);
            if ((lane & 3) == 0) {
                int row = wm * 32 + mf * 16 + (lane >> 2);
                sredw[row] = lo;
                sredw[row + 8] = hi;
            }
        }

        if (p + 1 < PASSES) {
            asm volatile("cp.async.wait_group 0;" ::: "memory");
            __syncthreads();
        }
    }
}

extern __shared__ char smem[];

__global__ __launch_bounds__(THREADS, 2)
void gmm_f16_kernel(const float* __restrict__ x, float* __restrict__ out) {
    const int tid = threadIdx.x;
    const int wid = tid >> 5;
    const int lane = tid & 31;
    const int wm = wid >> 2;          // 0..1 : 32-row M tile
    const int npair = wid & 3;        // i-chunk pair {npair, 7-npair}
    const uint32_t sbase = smem_u32(smem);

    // --- per-thread prefetch dst offsets (canonical enumeration) ---
    uint32_t pk0, pk1;
    {
        uint32_t offs[4];
        #pragma unroll
        for (int j = 0; j < 4; ++j) {
            int r, c;
            chunk_rc(tid + j * 256, r, c);
            offs[j] = (uint32_t)(r * XS_BYTES + c * 16);
        }
        pk0 = offs[0] | (offs[1] << 16);
        pk1 = offs[2] | (offs[3] << 16);
    }
    const uint32_t off4 =
        (uint32_t)((120 + (tid >> 4)) * XS_BYTES + (tid & 15) * 16);

    // --- prefetch L comp 0 ---
    prefetch_L(sbase + SM_L, (const char*)g_Lp + tid * 16, pk0, pk1, off4, tid);

    // --- stage X (fp32 -> fp16): 64 rows ---
    {
        const float4* xg = (const float4*)(x + (size_t)blockIdx.x * BR * D);
        #pragma unroll
        for (int i = 0; i < 8; ++i) {
            int f = tid + i * THREADS;
            float4 v = xg[f];
            __half2 h0 = __floats2half2_rn(v.x, v.y);
            __half2 h1 = __floats2half2_rn(v.z, v.w);
            int r = f >> 5, c4 = f & 31;
            *(uint2*)(smem + SM_X + r * XS_BYTES + c4 * 8) =
                make_uint2(*(uint32_t*)&h0, *(uint32_t*)&h1);
        }
    }
    // --- stage m, off ---
    {
        const float* gm = (const float*)g_m;
        #pragma unroll
        for (int i = 0; i < 8; ++i)
            ((float*)(smem + SM_M))[tid + i * THREADS] = gm[tid + i * THREADS];
        if (tid < NK) ((float*)(smem + SM_OFFS))[tid] = g_off[tid];
    }
    asm volatile("cp.async.wait_group 0;" ::: "memory");
    __syncthreads();

    const uint32_t a_lane = (uint32_t)((lane & 15) * XS_BYTES + (lane >> 4) * 16);
    const uint32_t b_lane = (uint32_t)(((lane >> 4) * 8 + (lane & 7)) * XS_BYTES +
                                       ((lane >> 3) & 1) * 16);
    const uint32_t aw = sbase + SM_X + wm * 32 * XS_BYTES + a_lane;

    // --- A fragments: 32 rows x K=128, loaded ONCE for all 16 components ---
    uint32_t afr[2][8][4];
    #pragma unroll
    for (int mf = 0; mf < 2; ++mf)
        #pragma unroll
        for (int s = 0; s < 8; ++s)
            ldsm_x4(afr[mf][s][0], afr[mf][s][1], afr[mf][s][2], afr[mf][s][3],
                    aw + mf * (16 * XS_BYTES) + s * 32);

    switch (npair) {
        case 0:  run_passes<7, 0>(afr, smem, sbase, b_lane, pk0, pk1, off4,
                                  tid, lane, wm); break;
        case 1:  run_passes<6, 1>(afr, smem, sbase, b_lane, pk0, pk1, off4,
                                  tid, lane, wm); break;
        case 2:  run_passes<5, 2>(afr, smem, sbase, b_lane, pk0, pk1, off4,
                                  tid, lane, wm); break;
        default: run_passes<4, 3>(afr, smem, sbase, b_lane, pk0, pk1, off4,
                                  tid, lane, wm); break;
    }

    __syncthreads();   // all SRED writes visible

    if (tid < BR) {
        const float* sred = (const float*)(smem + SM_SRED);
        const float* offs = (const float*)(smem + SM_OFFS);
        float v[NK], mx = -INFINITY;
        #pragma unroll
        for (int k = 0; k < NK; ++k) {
            float s = sred[k * BR + tid] + sred[(NK + k) * BR + tid] +
                      sred[(2 * NK + k) * BR + tid] +
                      sred[(3 * NK + k) * BR + tid];
            v[k] = offs[k] - 0.5f * s;
            mx = fmaxf(mx, v[k]);
        }
        float e = 0.f;
        #pragma unroll
        for (int k = 0; k < NK; ++k) e += expf(v[k] - mx);
        out[blockIdx.x * BR + tid] = mx + logf(e);
    }
}

extern "C" void kernel_launch(void* const* d_in, const int* in_sizes, int n_in,
                              void* d_out, int out_size) {
    const float* x     = (const float*)d_in[0];
    const float* means = (const float*)d_in[1];
    const float* prec  = (const float*)d_in[2];
    const float* logw  = (const float*)d_in[3];
    float* out = (float*)d_out;

    const int B = in_sizes[0] / D;

    gmm_prep_kernel<<<NK, 256>>>(means, prec, logw);

    cudaFuncSetAttribute(gmm_f16_kernel,
                         cudaFuncAttributeMaxDynamicSharedMemorySize, SM_TOTAL);
    gmm_f16_kernel<<<B / BR, THREADS, SM_TOTAL>>>(x, out);
}

// round 15
// speedup vs baseline: 1.3358x; 1.1055x over previous
#include <cuda_runtime.h>
#include <cuda_fp16.h>
#include <math.h>
#include <stdint.h>

// GMM log-likelihood via mma.sync fp16 (sm_100 baseline PTX).
// out[b] = logsumexp_k( off_k - 0.5*||L_k x_b - m_k||^2 ), m_k = L_k mu_k.
// L lower-triangular, packed densely per-component in global (canonical
// group enumeration). Warp-pair npair owns i-chunks {n, 7-n} = exactly 288
// 16B chunks (uniform across pairs): each pair prefetches ONLY its rows and
// syncs with a 64-thread NAMED barrier -> no block-wide per-pass barrier;
// the 4 pairs drift independently. MMA accumulators init to -m (epilogue =
// pure x*x). Fused-pair mainloop: 8 acc chains; A frags register-resident.
// BR=64, 256 threads, 2 CTAs/SM.

#define NK 16
#define D 128
#define BR 64
#define THREADS 256
#define PASSES 16

#define XS_BYTES 272
#define SM_X 0                               // 64*272 = 17408
#define SM_L 17408
#define LBUF_BYTES (128 * XS_BYTES)          // 34816 (1 comp)
#define SM_M (SM_L + 2 * LBUF_BYTES)         // 87040 : float m[16][128]
#define SM_OFFS (SM_M + NK * D * 4)          // 95232 : float off[16]
#define SM_SRED (SM_OFFS + 64)               // 95296 : float [4][16][64]
#define SM_TOTAL (SM_SRED + 4 * NK * BR * 4) // 111680

#define NCHUNK 1152                          // triangle chunks (16B each)
#define PACK_BYTES (NCHUNK * 16)             // 18432 per component

__device__ __half g_Lp[NK * NCHUNK * 8];     // packed triangle, fp16
__device__ float g_m[NK][D];
__device__ float g_off[NK];

// canonical chunk idx -> (row, chunk-col); group g = rows [16g,16g+16),
// 2g+2 chunks per row, group base = 16*(g*g+g).
__device__ __forceinline__ void chunk_rc(int idx, int& r, int& c) {
    int rem = idx;
    r = 0; c = 0;
    #pragma unroll
    for (int g = 0; g < 8; ++g) {
        int cnt = 16 * (2 * g + 2);
        if (rem >= 0 && rem < cnt) {
            r = 16 * g + rem / (2 * g + 2);
            c = rem % (2 * g + 2);
        }
        rem -= cnt;
    }
}

// ---------------- fused prep: pack fp16 triangle + m_k + off_k ----------------
__global__ void gmm_prep_kernel(const float* __restrict__ means,
                                const float* __restrict__ prec,
                                const float* __restrict__ logw) {
    const int k = blockIdx.x;
    const int tid = threadIdx.x;
    const int wid = tid >> 5, lane = tid & 31;
    const float* Lk = prec + (size_t)k * D * D;

    __shared__ float mu_s[D];
    __shared__ float red[D];

    if (tid < D) mu_s[tid] = means[k * D + tid];
    if (tid < D) red[tid] = logf(Lk[tid * D + tid]);

    for (int idx = tid; idx < NCHUNK; idx += THREADS) {
        int r, c;
        chunk_rc(idx, r, c);
        const float4* s = (const float4*)(Lk + r * D + c * 8);
        float4 v0 = s[0], v1 = s[1];
        __half2 h0 = __floats2half2_rn(v0.x, v0.y);
        __half2 h1 = __floats2half2_rn(v0.z, v0.w);
        __half2 h2 = __floats2half2_rn(v1.x, v1.y);
        __half2 h3 = __floats2half2_rn(v1.z, v1.w);
        uint4 o = make_uint4(*(uint32_t*)&h0, *(uint32_t*)&h1,
                             *(uint32_t*)&h2, *(uint32_t*)&h3);
        *(uint4*)(g_Lp + (size_t)k * NCHUNK * 8 + idx * 8) = o;
    }
    __syncthreads();

    for (int r = wid; r < D; r += 8) {
        float4 v = ((const float4*)(Lk + r * D))[lane];
        float4 m4 = *(const float4*)&mu_s[lane * 4];
        float d = v.x * m4.x + v.y * m4.y + v.z * m4.z + v.w * m4.w;
        #pragma unroll
        for (int o = 16; o > 0; o >>= 1) d += __shfl_xor_sync(~0u, d, o);
        if (lane == 0) g_m[k][r] = d;
    }

    for (int off = D / 2; off > 0; off >>= 1) {
        if (tid < off) red[tid] += red[tid + off];
        __syncthreads();
    }
    if (tid == 0)
        g_off[k] = logw[k] + red[0] - 64.0f * 1.8378770664093453f;
}

// ---------------- asm helpers ----------------
__device__ __forceinline__ uint32_t smem_u32(const void* p) {
    uint32_t a;
    asm("{ .reg .u64 t; cvta.to.shared.u64 t, %1; cvt.u32.u64 %0, t; }"
        : "=r"(a) : "l"(p));
    return a;
}
__device__ __forceinline__ void ldsm_x4(uint32_t& r0, uint32_t& r1,
                                        uint32_t& r2, uint32_t& r3,
                                        uint32_t addr) {
    asm volatile("ldmatrix.sync.aligned.m8n8.x4.shared.b16 {%0,%1,%2,%3}, [%4];"
                 : "=r"(r0), "=r"(r1), "=r"(r2), "=r"(r3) : "r"(addr));
}
__device__ __forceinline__ void mma_f16(float* c, uint32_t a0, uint32_t a1,
                                        uint32_t a2, uint32_t a3,
                                        uint32_t b0, uint32_t b1) {
    asm volatile(
        "mma.sync.aligned.m16n8k16.row.col.f32.f16.f16.f32 "
        "{%0,%1,%2,%3}, {%4,%5,%6,%7}, {%8,%9}, {%0,%1,%2,%3};"
        : "+f"(c[0]), "+f"(c[1]), "+f"(c[2]), "+f"(c[3])
        : "r"(a0), "r"(a1), "r"(a2), "r"(a3), "r"(b0), "r"(b1));
}
__device__ __forceinline__ void cp16(uint32_t dst, const void* src) {
    asm volatile("cp.async.cg.shared.global [%0], [%1], 16;"
                 :: "r"(dst), "l"(src) : "memory");
}

// Block-wide comp-0 prefetch (R14 style: linear src, precomputed dst).
__device__ __forceinline__ void prefetch_L0(uint32_t dstb, const char* srcp,
                                            uint32_t pk0, uint32_t pk1,
                                            uint32_t off4, int tid) {
    cp16(dstb + (pk0 & 0xFFFFu), srcp);
    cp16(dstb + (pk0 >> 16),     srcp + 4096);
    cp16(dstb + (pk1 & 0xFFFFu), srcp + 8192);
    cp16(dstb + (pk1 >> 16),     srcp + 12288);
    if (tid < 128) cp16(dstb + off4, srcp + 16384);
    asm volatile("cp.async.commit_group;" ::: "memory");
}

// Pair-local prefetch: 64 threads cover the pair's 288 chunks.
__device__ __forceinline__ void prefetch_pair(uint32_t dstb, const char* srcb,
                                              uint32_t dpk0, uint32_t dpk1,
                                              uint32_t spk0, uint32_t spk1,
                                              uint32_t doff4, uint32_t soff4,
                                              int wtid) {
    cp16(dstb + (dpk0 & 0xFFFFu), srcb + (spk0 & 0xFFFFu));
    cp16(dstb + (dpk0 >> 16),     srcb + (spk0 >> 16));
    cp16(dstb + (dpk1 & 0xFFFFu), srcb + (spk1 & 0xFFFFu));
    cp16(dstb + (dpk1 >> 16),     srcb + (spk1 >> 16));
    if (wtid < 32) cp16(dstb + doff4, srcb + soff4);
    asm volatile("cp.async.commit_group;" ::: "memory");
}

// Square-only epilogue (m folded into accumulator init).
__device__ __forceinline__ void epi_sq(const float acc[2][2][4],
                                       float rl[2], float rh[2]) {
    #pragma unroll
    for (int mf = 0; mf < 2; ++mf)
        #pragma unroll
        for (int nf = 0; nf < 2; ++nf) {
            rl[mf] = fmaf(acc[mf][nf][0], acc[mf][nf][0],
                     fmaf(acc[mf][nf][1], acc[mf][nf][1], rl[mf]));
            rh[mf] = fmaf(acc[mf][nf][2], acc[mf][nf][2],
                     fmaf(acc[mf][nf][3], acc[mf][nf][3], rh[mf]));
        }
}

// Fused pair {ICA, ICB} (ICA >= ICB): acc init -m; shared s-range runs both
// chunks' MMAs (8 chains); chunk-B epilogue early; tail = chunk A.
template <int ICA, int ICB>
__device__ __forceinline__ void do_pair(const uint32_t afr[2][8][4],
                                        uint32_t lb, const char* m_base,
                                        int lane, float rl[2], float rh[2]) {
    float2 mA0 = *(const float2*)(m_base + ICA * 64 + (lane & 3) * 8);
    float2 mA1 = *(const float2*)(m_base + ICA * 64 + 32 + (lane & 3) * 8);
    float2 mB0 = *(const float2*)(m_base + ICB * 64 + (lane & 3) * 8);
    float2 mB1 = *(const float2*)(m_base + ICB * 64 + 32 + (lane & 3) * 8);

    float accA[2][2][4], accB[2][2][4];
    #pragma unroll
    for (int mf = 0; mf < 2; ++mf) {
        accA[mf][0][0] = -mA0.x; accA[mf][0][1] = -mA0.y;
        accA[mf][0][2] = -mA0.x; accA[mf][0][3] = -mA0.y;
        accA[mf][1][0] = -mA1.x; accA[mf][1][1] = -mA1.y;
        accA[mf][1][2] = -mA1.x; accA[mf][1][3] = -mA1.y;
        accB[mf][0][0] = -mB0.x; accB[mf][0][1] = -mB0.y;
        accB[mf][0][2] = -mB0.x; accB[mf][0][3] = -mB0.y;
        accB[mf][1][0] = -mB1.x; accB[mf][1][1] = -mB1.y;
        accB[mf][1][2] = -mB1.x; accB[mf][1][3] = -mB1.y;
    }

    #pragma unroll
    for (int s = 0; s <= ICB; ++s) {
        uint32_t a0, a1, a2, a3, c0, c1, c2, c3;
        ldsm_x4(a0, a1, a2, a3, lb + ICA * (16 * XS_BYTES) + s * 32);
        ldsm_x4(c0, c1, c2, c3, lb + ICB * (16 * XS_BYTES) + s * 32);
        #pragma unroll
        for (int mf = 0; mf < 2; ++mf) {
            mma_f16(accA[mf][0], afr[mf][s][0], afr[mf][s][1], afr[mf][s][2],
                    afr[mf][s][3], a0, a1);
            mma_f16(accA[mf][1], afr[mf][s][0], afr[mf][s][1], afr[mf][s][2],
                    afr[mf][s][3], a2, a3);
            mma_f16(accB[mf][0], afr[mf][s][0], afr[mf][s][1], afr[mf][s][2],
                    afr[mf][s][3], c0, c1);
            mma_f16(accB[mf][1], afr[mf][s][0], afr[mf][s][1], afr[mf][s][2],
                    afr[mf][s][3], c2, c3);
        }
    }

    epi_sq(accB, rl, rh);   // accB dies here

    #pragma unroll
    for (int s = ICB + 1; s <= ICA; ++s) {
        uint32_t a0, a1, a2, a3;
        ldsm_x4(a0, a1, a2, a3, lb + ICA * (16 * XS_BYTES) + s * 32);
        #pragma unroll
        for (int mf = 0; mf < 2; ++mf) {
            mma_f16(accA[mf][0], afr[mf][s][0], afr[mf][s][1], afr[mf][s][2],
                    afr[mf][s][3], a0, a1);
            mma_f16(accA[mf][1], afr[mf][s][0], afr[mf][s][1], afr[mf][s][2],
                    afr[mf][s][3], a2, a3);
        }
    }

    epi_sq(accA, rl, rh);
}

// Pass loop for warp-pair role {ICA, ICB} (ICB == npair). Per-pass sync is a
// 64-thread named barrier (id = ICB+1) between the two partner warps only.
template <int ICA, int ICB>
__device__ __forceinline__ void run_passes(const uint32_t afr[2][8][4],
                                           char* smemc, uint32_t sbase,
                                           uint32_t b_lane,
                                           int wtid, int lane, int wm) {
    // pair-local prefetch offsets: linear chunk l = wtid + 64j over the
    // pair's canonical runs (group ICB first: 32*ICB+32 chunks, then ICA).
    uint32_t dpk0, dpk1, spk0, spk1, doff4 = 0, soff4 = 0;
    {
        uint32_t dtmp[4], stmp[4];
        #pragma unroll
        for (int j = 0; j < 4; ++j) {
            int l = wtid + 64 * j;
            int r, c; uint32_t so;
            if (l < 32 * ICB + 32) {
                r = 16 * ICB + l / (2 * ICB + 2);
                c = l % (2 * ICB + 2);
                so = (uint32_t)((16 * (ICB * ICB + ICB) + l) * 16);
            } else {
                int l2 = l - (32 * ICB + 32);
                r = 16 * ICA + l2 / (2 * ICA + 2);
                c = l2 % (2 * ICA + 2);
                so = (uint32_t)((16 * (ICA * ICA + ICA) + l2) * 16);
            }
            dtmp[j] = (uint32_t)(r * XS_BYTES + c * 16);
            stmp[j] = so;
        }
        dpk0 = dtmp[0] | (dtmp[1] << 16); dpk1 = dtmp[2] | (dtmp[3] << 16);
        spk0 = stmp[0] | (stmp[1] << 16); spk1 = stmp[2] | (stmp[3] << 16);
        if (wtid < 32) {
            int l = wtid + 256;   // >= 32*ICB+32 for all ICB<=3... 
            // l=256..287; group-ICB run has 32*ICB+32 <= 128 chunks for
            // ICB<=3, so l is always in the ICA run.
            int l2 = l - (32 * ICB + 32);
            int r = 16 * ICA + l2 / (2 * ICA + 2);
            int c = l2 % (2 * ICA + 2);
            doff4 = (uint32_t)(r * XS_BYTES + c * 16);
            soff4 = (uint32_t)((16 * (ICA * ICA + ICA) + l2) * 16);
        }
    }

    #pragma unroll 1
    for (int p = 0; p < PASSES; ++p) {
        if (p + 1 < PASSES)
            prefetch_pair(sbase + SM_L + ((p + 1) & 1) * LBUF_BYTES,
                          (const char*)g_Lp + (size_t)(p + 1) * PACK_BYTES,
                          dpk0, dpk1, spk0, spk1, doff4, soff4, wtid);

        const uint32_t lb = sbase + SM_L + (p & 1) * LBUF_BYTES + b_lane;
        const char* m_base = smemc + SM_M + p * 512;

        float rl[2] = {0.f, 0.f}, rh[2] = {0.f, 0.f};
        do_pair<ICA, ICB>(afr, lb, m_base, lane, rl, rh);

        float* sredw = (float*)(smemc + SM_SRED) + (ICB * NK + p) * BR;
        #pragma unroll
        for (int mf = 0; mf < 2; ++mf) {
            float lo = rl[mf], hi = rh[mf];
            lo += __shfl_xor_sync(~0u, lo, 1);
            lo += __shfl_xor_sync(~0u, lo, 2);
            hi += __shfl_xor_sync(~0u, hi, 1);
            hi += __shfl_xor_sync(~0u, hi, 2);
            if ((lane & 3) == 0) {
                int row = wm * 32 + mf * 16 + (lane >> 2);
                sredw[row] = lo;
                sredw[row + 8] = hi;
            }
        }

        if (p + 1 < PASSES) {
            asm volatile("cp.async.wait_group 0;" ::: "memory");
            asm volatile("bar.sync %0, 64;" :: "r"(ICB + 1) : "memory");
        }
    }
}

extern __shared__ char smem[];

__global__ __launch_bounds__(THREADS, 2)
void gmm_f16_kernel(const float* __restrict__ x, float* __restrict__ out) {
    const int tid = threadIdx.x;
    const int wid = tid >> 5;
    const int lane = tid & 31;
    const int wm = wid >> 2;          // 0..1 : 32-row M tile
    const int npair = wid & 3;        // i-chunk pair {npair, 7-npair}
    const int wtid = wm * 32 + lane;  // 0..63 within pair
    const uint32_t sbase = smem_u32(smem);

    // --- comp-0 block-wide prefetch offsets (canonical enumeration) ---
    uint32_t pk0, pk1;
    {
        uint32_t offs[4];
        #pragma unroll
        for (int j = 0; j < 4; ++j) {
            int r, c;
            chunk_rc(tid + j * 256, r, c);
            offs[j] = (uint32_t)(r * XS_BYTES + c * 16);
        }
        pk0 = offs[0] | (offs[1] << 16);
        pk1 = offs[2] | (offs[3] << 16);
    }
    const uint32_t off4 =
        (uint32_t)((120 + (tid >> 4)) * XS_BYTES + (tid & 15) * 16);

    prefetch_L0(sbase + SM_L, (const char*)g_Lp + tid * 16, pk0, pk1, off4, tid);

    // --- stage X (fp32 -> fp16): 64 rows ---
    {
        const float4* xg = (const float4*)(x + (size_t)blockIdx.x * BR * D);
        #pragma unroll
        for (int i = 0; i < 8; ++i) {
            int f = tid + i * THREADS;
            float4 v = xg[f];
            __half2 h0 = __floats2half2_rn(v.x, v.y);
            __half2 h1 = __floats2half2_rn(v.z, v.w);
            int r = f >> 5, c4 = f & 31;
            *(uint2*)(smem + SM_X + r * XS_BYTES + c4 * 8) =
                make_uint2(*(uint32_t*)&h0, *(uint32_t*)&h1);
        }
    }
    // --- stage m, off ---
    {
        const float* gm = (const float*)g_m;
        #pragma unroll
        for (int i = 0; i < 8; ++i)
            ((float*)(smem + SM_M))[tid + i * THREADS] = gm[tid + i * THREADS];
        if (tid < NK) ((float*)(smem + SM_OFFS))[tid] = g_off[tid];
    }
    asm volatile("cp.async.wait_group 0;" ::: "memory");
    __syncthreads();   // X + comp-0 L + m visible to all

    const uint32_t a_lane = (uint32_t)((lane & 15) * XS_BYTES + (lane >> 4) * 16);
    const uint32_t b_lane = (uint32_t)(((lane >> 4) * 8 + (lane & 7)) * XS_BYTES +
                                       ((lane >> 3) & 1) * 16);
    const uint32_t aw = sbase + SM_X + wm * 32 * XS_BYTES + a_lane;

    // --- A fragments: 32 rows x K=128, loaded ONCE for all 16 components ---
    uint32_t afr[2][8][4];
    #pragma unroll
    for (int mf = 0; mf < 2; ++mf)
        #pragma unroll
        for (int s = 0; s < 8; ++s)
            ldsm_x4(afr[mf][s][0], afr[mf][s][1], afr[mf][s][2], afr[mf][s][3],
                    aw + mf * (16 * XS_BYTES) + s * 32);

    switch (npair) {
        case 0:  run_passes<7, 0>(afr, smem, sbase, b_lane, wtid, lane, wm);
                 break;
        case 1:  run_passes<6, 1>(afr, smem, sbase, b_lane, wtid, lane, wm);
                 break;
        case 2:  run_passes<5, 2>(afr, smem, sbase, b_lane, wtid, lane, wm);
                 break;
        default: run_passes<4, 3>(afr, smem, sbase, b_lane, wtid, lane, wm);
                 break;
    }

    __syncthreads();   // all pairs' SRED writes visible

    if (tid < BR) {
        const float* sred = (const float*)(smem + SM_SRED);
        const float* offs = (const float*)(smem + SM_OFFS);
        float v[NK], mx = -INFINITY;
        #pragma unroll
        for (int k = 0; k < NK; ++k) {
            float s = sred[k * BR + tid] + sred[(NK + k) * BR + tid] +
                      sred[(2 * NK + k) * BR + tid] +
                      sred[(3 * NK + k) * BR + tid];
            v[k] = offs[k] - 0.5f * s;
            mx = fmaxf(mx, v[k]);
        }
        float e = 0.f;
        #pragma unroll
        for (int k = 0; k < NK; ++k) e += expf(v[k] - mx);
        out[blockIdx.x * BR + tid] = mx + logf(e);
    }
}

extern "C" void kernel_launch(void* const* d_in, const int* in_sizes, int n_in,
                              void* d_out, int out_size) {
    const float* x     = (const float*)d_in[0];
    const float* means = (const float*)d_in[1];
    const float* prec  = (const float*)d_in[2];
    const float* logw  = (const float*)d_in[3];
    float* out = (float*)d_out;

    const int B = in_sizes[0] / D;

    gmm_prep_kernel<<<NK, 256>>>(means, prec, logw);

    cudaFuncSetAttribute(gmm_f16_kernel,
                         cudaFuncAttributeMaxDynamicSharedMemorySize, SM_TOTAL);
    gmm_f16_kernel<<<B / BR, THREADS, SM_TOTAL>>>(x, out);
}